// round 8
// baseline (speedup 1.0000x reference)
#include <cuda_runtime.h>
#include <math.h>

// ---------------- problem constants ----------------
#define BATCH 4
#define TSEQ  2048
#define CDIM  768
#define HNUM  12
#define DHEAD 64
#define EXP   8
#define TOPK  2
#define DFF   3072
#define QKVDIM 2304
#define NTOK  (BATCH*TSEQ)          // 8192
#define NSLOT (NTOK*TOPK)           // 16384

// ---------------- scratch buffers (device globals; allocation-free) ----------------
__device__ __align__(16) float g_h  [(size_t)NTOK*CDIM];
__device__ __align__(16) float g_qkv[(size_t)NTOK*QKVDIM];
__device__ __align__(16) float g_y  [(size_t)NTOK*CDIM];
__device__ __align__(16) float g_x1 [(size_t)NTOK*CDIM];
__device__ __align__(16) float g_z  [(size_t)NTOK*CDIM];
__device__ __align__(16) float g_hid[(size_t)NSLOT*DFF];     // ~201 MB
__device__ __align__(16) float g_ye [(size_t)NSLOT*CDIM];    // ~50 MB
__device__ __align__(16) float g_wts[NSLOT];
__device__ int   g_eidx[NSLOT];
__device__ int   g_cnt [EXP];
__device__ int   g_eoff[EXP+1];
__device__ int   g_fill[EXP];
__device__ int   g_perm[NSLOT];

// ---------------- LayerNorm: one block (256 thr) per token ----------------
__global__ void ln_kernel(const float* __restrict__ x, const float* __restrict__ g,
                          const float* __restrict__ bta, float* __restrict__ out)
{
    int n = blockIdx.x, tid = threadIdx.x;
    const float* row = x + (size_t)n*CDIM;
    float v[3]; float s = 0.f, sq = 0.f;
#pragma unroll
    for (int i = 0; i < 3; i++) { v[i] = row[tid + i*256]; s += v[i]; sq += v[i]*v[i]; }
#pragma unroll
    for (int off = 16; off; off >>= 1) {
        s  += __shfl_xor_sync(0xffffffffu, s,  off);
        sq += __shfl_xor_sync(0xffffffffu, sq, off);
    }
    __shared__ float ss[8], sqs[8];
    int warp = tid >> 5, lane = tid & 31;
    if (lane == 0) { ss[warp] = s; sqs[warp] = sq; }
    __syncthreads();
    float tot = 0.f, totq = 0.f;
#pragma unroll
    for (int w = 0; w < 8; w++) { tot += ss[w]; totq += sqs[w]; }
    float mean = tot * (1.0f/CDIM);
    float var  = totq * (1.0f/CDIM) - mean*mean;
    float rstd = rsqrtf(var + 1e-5f);
    float* orow = out + (size_t)n*CDIM;
#pragma unroll
    for (int i = 0; i < 3; i++) {
        int c = tid + i*256;
        orow[c] = (v[i] - mean) * rstd * g[c] + bta[c];
    }
}

// ---------------- SGEMM: 128x128x16 tiles, 256 threads, 8x8 microtile ----------------
// Double-buffered smem pipeline: ONE __syncthreads per K-tile, global prefetch
// into registers overlapped with FFMA on the current tile.
// MODE 0: C = A@B + bias                    (dense)
// MODE 1: C = A@B + bias + Res              (dense, residual)
// MODE 2: C = relu(gather(A)@B[e] + b[e])   (grouped; A row = perm[p]>>1; out row = p)
// MODE 3: C[perm[p]] = w[perm[p]]*(A[p]@B[e] + b[e])  (grouped scatter)
#define BM 128
#define BN 128
#define BK 16

template<int MODE>
__global__ __launch_bounds__(256)
void sgemm_kernel(const float* __restrict__ A, const float* __restrict__ Bw,
                  const float* __restrict__ bias, const float* __restrict__ Res,
                  float* __restrict__ Cout, int M, int N, int Kd,
                  const int* __restrict__ perm, const int* __restrict__ eoff,
                  const float* __restrict__ wts)
{
    __shared__ __align__(16) float As[2][BK][BM+4];
    __shared__ __align__(16) float Bs[2][BK][BN];
    __shared__ int rowIdx[BM];

    int Mloc = M, mbase = 0;
    const float* Bp = Bw;
    const float* biasp = bias;
    if (MODE >= 2) {
        int e = blockIdx.z;
        int p0 = eoff[e];
        Mloc  = eoff[e+1] - p0;
        mbase = p0;
        Bp    = Bw   + (size_t)e * Kd * N;
        biasp = bias + (size_t)e * N;
    }
    int tM = blockIdx.y * BM;
    if (tM >= Mloc) return;
    int tN = blockIdx.x * BN;

    int tid = threadIdx.x;
    if (tid < BM) {
        int r = tM + tid;
        int src = -1;
        if (r < Mloc) {
            if (MODE == 2)      src = perm[mbase + r] >> 1;  // token index
            else if (MODE == 3) src = mbase + r;             // hid row
            else                src = r;
        }
        rowIdx[tid] = src;
    }
    __syncthreads();

    // per-thread load coordinates (hoisted out of the K loop)
    int arow[2], akq[2];
    const float* aptr[2];
    int bkr[2], bnq[2];
    const float* bptr[2];
#pragma unroll
    for (int l = 0; l < 2; l++) {
        int idx = tid + 256*l;
        arow[l] = idx >> 2; akq[l] = idx & 3;
        int src = rowIdx[arow[l]];
        aptr[l] = (src >= 0) ? (A + (size_t)src*Kd + akq[l]*4) : nullptr;
        bkr[l] = idx >> 5; bnq[l] = idx & 31;
        bptr[l] = Bp + (size_t)bkr[l]*N + tN + bnq[l]*4;
    }

    // prologue: tile 0 -> buffer 0
#pragma unroll
    for (int l = 0; l < 2; l++) {
        float4 v = make_float4(0.f,0.f,0.f,0.f);
        if (aptr[l]) v = *(const float4*)(aptr[l]);
        As[0][akq[l]*4+0][arow[l]] = v.x; As[0][akq[l]*4+1][arow[l]] = v.y;
        As[0][akq[l]*4+2][arow[l]] = v.z; As[0][akq[l]*4+3][arow[l]] = v.w;
        *(float4*)&Bs[0][bkr[l]][bnq[l]*4] = *(const float4*)(bptr[l]);
    }
    __syncthreads();

    int tx = tid & 15, ty = tid >> 4;
    float acc[8][8];
#pragma unroll
    for (int i = 0; i < 8; i++)
#pragma unroll
        for (int j = 0; j < 8; j++) acc[i][j] = 0.f;

    int nIter = Kd / BK;
    int cur = 0;
    for (int it = 0; it < nIter; it++) {
        float4 av[2], bv[2];
        bool hasNext = (it + 1 < nIter);
        if (hasNext) {
            size_t koff = (size_t)(it + 1) * BK;
#pragma unroll
            for (int l = 0; l < 2; l++) {
                av[l] = make_float4(0.f,0.f,0.f,0.f);
                if (aptr[l]) av[l] = *(const float4*)(aptr[l] + koff);
                bv[l] = *(const float4*)(bptr[l] + koff * N);
            }
        }
        const float* asb = &As[cur][0][0];
        const float* bsb = &Bs[cur][0][0];
#pragma unroll
        for (int k = 0; k < BK; k++) {
            float a[8], b[8];
            *(float4*)&a[0] = *(const float4*)(asb + k*(BM+4) + ty*8);
            *(float4*)&a[4] = *(const float4*)(asb + k*(BM+4) + ty*8 + 4);
            *(float4*)&b[0] = *(const float4*)(bsb + k*BN + tx*8);
            *(float4*)&b[4] = *(const float4*)(bsb + k*BN + tx*8 + 4);
#pragma unroll
            for (int i = 0; i < 8; i++)
#pragma unroll
                for (int j = 0; j < 8; j++) acc[i][j] += a[i]*b[j];
        }
        if (hasNext) {
            int nxt = cur ^ 1;
#pragma unroll
            for (int l = 0; l < 2; l++) {
                As[nxt][akq[l]*4+0][arow[l]] = av[l].x;
                As[nxt][akq[l]*4+1][arow[l]] = av[l].y;
                As[nxt][akq[l]*4+2][arow[l]] = av[l].z;
                As[nxt][akq[l]*4+3][arow[l]] = av[l].w;
                *(float4*)&Bs[nxt][bkr[l]][bnq[l]*4] = bv[l];
            }
            __syncthreads();
            cur = nxt;
        }
    }

    // epilogue
    float4 bv0 = *(const float4*)(biasp + tN + tx*8);
    float4 bv1 = *(const float4*)(biasp + tN + tx*8 + 4);
#pragma unroll
    for (int i = 0; i < 8; i++) {
        int rloc = tM + ty*8 + i;
        if (rloc >= Mloc) break;
        float o[8];
        o[0]=acc[i][0]+bv0.x; o[1]=acc[i][1]+bv0.y; o[2]=acc[i][2]+bv0.z; o[3]=acc[i][3]+bv0.w;
        o[4]=acc[i][4]+bv1.x; o[5]=acc[i][5]+bv1.y; o[6]=acc[i][6]+bv1.z; o[7]=acc[i][7]+bv1.w;
        size_t coff;
        if (MODE == 0 || MODE == 1) {
            coff = (size_t)rloc*N + tN + tx*8;
            if (MODE == 1) {
                const float* rr = Res + coff;
#pragma unroll
                for (int j = 0; j < 8; j++) o[j] += rr[j];
            }
        } else if (MODE == 2) {
#pragma unroll
            for (int j = 0; j < 8; j++) o[j] = fmaxf(o[j], 0.f);
            coff = (size_t)(mbase + rloc)*N + tN + tx*8;
        } else { // MODE 3
            int a = perm[mbase + rloc];
            float wt = wts[a];
#pragma unroll
            for (int j = 0; j < 8; j++) o[j] *= wt;
            coff = (size_t)a*N + tN + tx*8;
        }
        float4 s0 = make_float4(o[0],o[1],o[2],o[3]);
        float4 s1 = make_float4(o[4],o[5],o[6],o[7]);
        *(float4*)(Cout + coff)     = s0;
        *(float4*)(Cout + coff + 4) = s1;
    }
}

// ---------------- flash attention (fp32, causal), 64x64 tiles, D=64 ----------------
// smem: Qs[d][r] (65 stride), KPs: K as [d][c] then P as [s][r] (65), Vs[s][c] (64)
// NOTE: 65-float stride (260 B) is NOT 16B-periodic -> all reads on that stride
// are SCALAR loads (alignment-safe; worst case 2-way bank conflicts).
#define ATTN_SMEM ((64*65*2 + 64*64)*4)

__global__ __launch_bounds__(256)
void attn_kernel(const float* __restrict__ qkv, float* __restrict__ y)
{
    extern __shared__ float sm[];
    float* Qs  = sm;
    float* KPs = sm + 64*65;
    float* Vs  = sm + 2*64*65;

    int tid = threadIdx.x;
    int tx = tid & 15, ty = tid >> 4;
    int bh = blockIdx.y;
    int b = bh / HNUM, h = bh % HNUM;
    int qt = blockIdx.x;
    const float* qb = qkv + (size_t)b*TSEQ*QKVDIM + h*DHEAD;
    const float* kb = qb + CDIM;
    const float* vb = qb + 2*CDIM;

    // load Q tile transposed: Qs[d][r]
#pragma unroll
    for (int p = 0; p < 4; p++) {
        int r = p*16 + ty;
        float4 v = *(const float4*)(qb + (size_t)(qt*64 + r)*QKVDIM + tx*4);
        Qs[(tx*4+0)*65 + r] = v.x; Qs[(tx*4+1)*65 + r] = v.y;
        Qs[(tx*4+2)*65 + r] = v.z; Qs[(tx*4+3)*65 + r] = v.w;
    }

    float o[4][4];
    float mrow[4], lrow[4];
#pragma unroll
    for (int i = 0; i < 4; i++) {
        mrow[i] = -INFINITY; lrow[i] = 0.f;
#pragma unroll
        for (int j = 0; j < 4; j++) o[i][j] = 0.f;
    }

    for (int kt = 0; kt <= qt; kt++) {
        __syncthreads();   // previous iteration consumers done
#pragma unroll
        for (int p = 0; p < 4; p++) {  // K transposed, V natural
            int r = p*16 + ty;
            float4 kv = *(const float4*)(kb + (size_t)(kt*64 + r)*QKVDIM + tx*4);
            KPs[(tx*4+0)*65 + r] = kv.x; KPs[(tx*4+1)*65 + r] = kv.y;
            KPs[(tx*4+2)*65 + r] = kv.z; KPs[(tx*4+3)*65 + r] = kv.w;
            float4 vv = *(const float4*)(vb + (size_t)(kt*64 + r)*QKVDIM + tx*4);
            *(float4*)&Vs[r*64 + tx*4] = vv;
        }
        __syncthreads();

        float s[4][4];
#pragma unroll
        for (int i = 0; i < 4; i++)
#pragma unroll
            for (int j = 0; j < 4; j++) s[i][j] = 0.f;
#pragma unroll
        for (int d = 0; d < 64; d++) {
            float a[4], bq[4];
#pragma unroll
            for (int i = 0; i < 4; i++) a[i]  = Qs [d*65 + ty*4 + i];   // scalar (260B stride)
#pragma unroll
            for (int j = 0; j < 4; j++) bq[j] = KPs[d*65 + tx*4 + j];   // scalar
#pragma unroll
            for (int i = 0; i < 4; i++)
#pragma unroll
                for (int j = 0; j < 4; j++) s[i][j] += a[i]*bq[j];
        }
#pragma unroll
        for (int i = 0; i < 4; i++)
#pragma unroll
            for (int j = 0; j < 4; j++) s[i][j] *= 0.125f;
        if (kt == qt) {
#pragma unroll
            for (int i = 0; i < 4; i++)
#pragma unroll
                for (int j = 0; j < 4; j++)
                    if (tx*4 + j > ty*4 + i) s[i][j] = -INFINITY;
        }
        __syncthreads();   // done reading K before overwriting with P

#pragma unroll
        for (int i = 0; i < 4; i++) {
            float mx = fmaxf(fmaxf(s[i][0], s[i][1]), fmaxf(s[i][2], s[i][3]));
#pragma unroll
            for (int off = 1; off < 16; off <<= 1)
                mx = fmaxf(mx, __shfl_xor_sync(0xffffffffu, mx, off));
            float mnew = fmaxf(mrow[i], mx);
            float corr = __expf(mrow[i] - mnew);
            float rs = 0.f;
#pragma unroll
            for (int j = 0; j < 4; j++) { s[i][j] = __expf(s[i][j] - mnew); rs += s[i][j]; }
#pragma unroll
            for (int off = 1; off < 16; off <<= 1)
                rs += __shfl_xor_sync(0xffffffffu, rs, off);
            lrow[i] = lrow[i]*corr + rs;
            mrow[i] = mnew;
#pragma unroll
            for (int j = 0; j < 4; j++) o[i][j] *= corr;
#pragma unroll
            for (int j = 0; j < 4; j++)
                KPs[(tx*4+j)*65 + (ty*4+i)] = s[i][j];  // P[s][r]
        }
        __syncthreads();

#pragma unroll
        for (int ss = 0; ss < 64; ss++) {
            float a[4], bv[4];
#pragma unroll
            for (int i = 0; i < 4; i++) a[i] = KPs[ss*65 + ty*4 + i];   // scalar (260B stride)
            *(float4*)bv = *(const float4*)&Vs[ss*64 + tx*4];           // aligned (256B stride)
#pragma unroll
            for (int i = 0; i < 4; i++)
#pragma unroll
                for (int j = 0; j < 4; j++) o[i][j] += a[i]*bv[j];
        }
    }

#pragma unroll
    for (int i = 0; i < 4; i++) {
        float inv = 1.0f / lrow[i];
        int row = qt*64 + ty*4 + i;
        float4 ov = make_float4(o[i][0]*inv, o[i][1]*inv, o[i][2]*inv, o[i][3]*inv);
        *(float4*)(y + ((size_t)b*TSEQ + row)*CDIM + h*DHEAD + tx*4) = ov;
    }
}

// ---------------- router: one block per token, top-2 + softmax ----------------
__global__ void router_kernel(const float* __restrict__ z, const float* __restrict__ Wr,
                              const float* __restrict__ br, int* __restrict__ eidx,
                              float* __restrict__ wts, int* __restrict__ cnt)
{
    int n = blockIdx.x, tid = threadIdx.x;
    float acc[EXP];
#pragma unroll
    for (int e = 0; e < EXP; e++) acc[e] = 0.f;
    const float* zr = z + (size_t)n*CDIM;
    for (int c = tid; c < CDIM; c += 256) {
        float zv = zr[c];
        const float* wr = Wr + c*EXP;
#pragma unroll
        for (int e = 0; e < EXP; e++) acc[e] += zv * wr[e];
    }
#pragma unroll
    for (int e = 0; e < EXP; e++)
#pragma unroll
        for (int off = 16; off; off >>= 1)
            acc[e] += __shfl_xor_sync(0xffffffffu, acc[e], off);
    __shared__ float red[8][EXP];
    int warp = tid >> 5, lane = tid & 31;
    if (lane == 0)
#pragma unroll
        for (int e = 0; e < EXP; e++) red[warp][e] = acc[e];
    __syncthreads();
    if (tid == 0) {
        float l[EXP];
#pragma unroll
        for (int e = 0; e < EXP; e++) {
            float sv = br[e];
#pragma unroll
            for (int w = 0; w < 8; w++) sv += red[w][e];
            l[e] = sv;
        }
        int i1 = 0;
#pragma unroll
        for (int e = 1; e < EXP; e++) if (l[e] > l[i1]) i1 = e;
        int i2 = -1;
#pragma unroll
        for (int e = 0; e < EXP; e++) {
            if (e == i1) continue;
            if (i2 < 0 || l[e] > l[i2]) i2 = e;
        }
        float e2 = __expf(l[i2] - l[i1]);
        float inv = 1.0f / (1.0f + e2);
        eidx[n*2]   = i1;  eidx[n*2+1] = i2;
        wts [n*2]   = inv; wts [n*2+1] = e2*inv;
        atomicAdd(&cnt[i1], 1);
        atomicAdd(&cnt[i2], 1);
    }
}

__global__ void zero_kernel(int* cnt) { if (threadIdx.x < EXP) cnt[threadIdx.x] = 0; }

__global__ void scan_kernel(const int* __restrict__ cnt, int* __restrict__ eoff,
                            int* __restrict__ fill)
{
    if (threadIdx.x == 0) {
        int s = 0;
        for (int e = 0; e < EXP; e++) { eoff[e] = s; fill[e] = s; s += cnt[e]; }
        eoff[EXP] = s;
    }
}

__global__ void scatter_kernel(const int* __restrict__ eidx, int* __restrict__ fill,
                               int* __restrict__ perm)
{
    int a = blockIdx.x*256 + threadIdx.x;
    if (a >= NSLOT) return;
    int e = eidx[a];
    int pos = atomicAdd(&fill[e], 1);
    perm[pos] = a;
}

// ---------------- final combine: out = x1 + ye[tok,0] + ye[tok,1] ----------------
__global__ void combine_kernel(const float* __restrict__ x1, const float* __restrict__ ye,
                               float* __restrict__ out)
{
    int i = blockIdx.x*256 + threadIdx.x;
    if (i >= NTOK*(CDIM/4)) return;
    int n = i / (CDIM/4), c4 = i % (CDIM/4);
    size_t co = (size_t)c4*4;
    float4 a  = *(const float4*)(x1 + (size_t)n*CDIM + co);
    float4 y0 = *(const float4*)(ye + (size_t)(n*2)  *CDIM + co);
    float4 y1 = *(const float4*)(ye + (size_t)(n*2+1)*CDIM + co);
    a.x += y0.x + y1.x; a.y += y0.y + y1.y;
    a.z += y0.z + y1.z; a.w += y0.w + y1.w;
    *(float4*)(out + (size_t)n*CDIM + co) = a;
}

// ---------------- launch ----------------
extern "C" void kernel_launch(void* const* d_in, const int* in_sizes, int n_in,
                              void* d_out, int out_size)
{
    (void)in_sizes; (void)n_in; (void)out_size;
    const float* x      = (const float*)d_in[0];
    const float* ln1_g  = (const float*)d_in[1];
    const float* ln1_b  = (const float*)d_in[2];
    const float* Wqkv   = (const float*)d_in[3];
    const float* bqkv   = (const float*)d_in[4];
    const float* Wproj  = (const float*)d_in[5];
    const float* bproj  = (const float*)d_in[6];
    const float* ln2_g  = (const float*)d_in[7];
    const float* ln2_b  = (const float*)d_in[8];
    const float* Wr     = (const float*)d_in[9];
    const float* br     = (const float*)d_in[10];
    const float* W1     = (const float*)d_in[11];
    const float* b1     = (const float*)d_in[12];
    const float* W2     = (const float*)d_in[13];
    const float* b2     = (const float*)d_in[14];
    float* out = (float*)d_out;

    float *h,*qkv,*y,*x1,*z,*hid,*ye,*wts;
    int *eidx,*cnt,*eoff,*fill,*perm;
    cudaGetSymbolAddress((void**)&h,   g_h);
    cudaGetSymbolAddress((void**)&qkv, g_qkv);
    cudaGetSymbolAddress((void**)&y,   g_y);
    cudaGetSymbolAddress((void**)&x1,  g_x1);
    cudaGetSymbolAddress((void**)&z,   g_z);
    cudaGetSymbolAddress((void**)&hid, g_hid);
    cudaGetSymbolAddress((void**)&ye,  g_ye);
    cudaGetSymbolAddress((void**)&wts, g_wts);
    cudaGetSymbolAddress((void**)&eidx,g_eidx);
    cudaGetSymbolAddress((void**)&cnt, g_cnt);
    cudaGetSymbolAddress((void**)&eoff,g_eoff);
    cudaGetSymbolAddress((void**)&fill,g_fill);
    cudaGetSymbolAddress((void**)&perm,g_perm);

    cudaFuncSetAttribute(attn_kernel, cudaFuncAttributeMaxDynamicSharedMemorySize, ATTN_SMEM);

    // 1. LN1
    ln_kernel<<<NTOK, 256>>>(x, ln1_g, ln1_b, h);
    // 2. QKV projection
    sgemm_kernel<0><<<dim3(QKVDIM/BN, NTOK/BM), 256>>>(h, Wqkv, bqkv, nullptr, qkv,
                                                       NTOK, QKVDIM, CDIM,
                                                       nullptr, nullptr, nullptr);
    // 3. causal flash attention
    attn_kernel<<<dim3(TSEQ/64, BATCH*HNUM), 256, ATTN_SMEM>>>(qkv, y);
    // 4. output projection + residual
    sgemm_kernel<1><<<dim3(CDIM/BN, NTOK/BM), 256>>>(y, Wproj, bproj, x, x1,
                                                     NTOK, CDIM, CDIM,
                                                     nullptr, nullptr, nullptr);
    // 5. LN2
    ln_kernel<<<NTOK, 256>>>(x1, ln2_g, ln2_b, z);
    // 6. router top-2
    zero_kernel<<<1, 32>>>(cnt);
    router_kernel<<<NTOK, 256>>>(z, Wr, br, eidx, wts, cnt);
    scan_kernel<<<1, 32>>>(cnt, eoff, fill);
    scatter_kernel<<<(NSLOT+255)/256, 256>>>(eidx, fill, perm);
    // 7. grouped expert GEMM1 (gather + relu)
    sgemm_kernel<2><<<dim3(DFF/BN, NTOK/BM, EXP), 256>>>(z, W1, b1, nullptr, hid,
                                                         0, DFF, CDIM, perm, eoff, nullptr);
    // 8. grouped expert GEMM2 (scatter with gate weight)
    sgemm_kernel<3><<<dim3(CDIM/BN, NTOK/BM, EXP), 256>>>(hid, W2, b2, nullptr, ye,
                                                          0, CDIM, DFF, perm, eoff, wts);
    // 9. combine
    combine_kernel<<<(NTOK*(CDIM/4)+255)/256, 256>>>(x1, ye, out);
}

// round 15
// speedup vs baseline: 1.9652x; 1.9652x over previous
#include <cuda_runtime.h>
#include <math.h>
#include <stdint.h>

// ---------------- problem constants ----------------
#define BATCH 4
#define TSEQ  2048
#define CDIM  768
#define HNUM  12
#define DHEAD 64
#define EXP   8
#define TOPK  2
#define DFF   3072
#define QKVDIM 2304
#define NTOK  (BATCH*TSEQ)          // 8192
#define NSLOT (NTOK*TOPK)           // 16384

// ---------------- scratch buffers (device globals; allocation-free) ----------------
__device__ __align__(16) float g_h  [(size_t)NTOK*CDIM];
__device__ __align__(16) float g_qkv[(size_t)NTOK*QKVDIM];
__device__ __align__(16) float g_y  [(size_t)NTOK*CDIM];
__device__ __align__(16) float g_x1 [(size_t)NTOK*CDIM];
__device__ __align__(16) float g_z  [(size_t)NTOK*CDIM];
__device__ __align__(16) float g_hid[(size_t)NSLOT*DFF];     // ~201 MB
__device__ __align__(16) float g_ye [(size_t)NSLOT*CDIM];    // ~50 MB
__device__ __align__(16) float g_wts[NSLOT];
__device__ int   g_eidx[NSLOT];
__device__ int   g_cnt [EXP];
__device__ int   g_eoff[EXP+1];
__device__ int   g_fill[EXP];
__device__ int   g_perm[NSLOT];

// ---------------- LayerNorm: one block (256 thr) per token ----------------
__global__ void ln_kernel(const float* __restrict__ x, const float* __restrict__ g,
                          const float* __restrict__ bta, float* __restrict__ out)
{
    int n = blockIdx.x, tid = threadIdx.x;
    const float* row = x + (size_t)n*CDIM;
    float v[3]; float s = 0.f, sq = 0.f;
#pragma unroll
    for (int i = 0; i < 3; i++) { v[i] = row[tid + i*256]; s += v[i]; sq += v[i]*v[i]; }
#pragma unroll
    for (int off = 16; off; off >>= 1) {
        s  += __shfl_xor_sync(0xffffffffu, s,  off);
        sq += __shfl_xor_sync(0xffffffffu, sq, off);
    }
    __shared__ float ss[8], sqs[8];
    int warp = tid >> 5, lane = tid & 31;
    if (lane == 0) { ss[warp] = s; sqs[warp] = sq; }
    __syncthreads();
    float tot = 0.f, totq = 0.f;
#pragma unroll
    for (int w = 0; w < 8; w++) { tot += ss[w]; totq += sqs[w]; }
    float mean = tot * (1.0f/CDIM);
    float var  = totq * (1.0f/CDIM) - mean*mean;
    float rstd = rsqrtf(var + 1e-5f);
    float* orow = out + (size_t)n*CDIM;
#pragma unroll
    for (int i = 0; i < 3; i++) {
        int c = tid + i*256;
        orow[c] = (v[i] - mean) * rstd * g[c] + bta[c];
    }
}

// ---------------- fp32 SGEMM (kept for QKV + proj: router-critical path) ----------
// MODE 0: C = A@B + bias ; MODE 1: C = A@B + bias + Res
#define BM 128
#define BN 128
#define BK 16

template<int MODE>
__global__ __launch_bounds__(256)
void sgemm_kernel(const float* __restrict__ A, const float* __restrict__ Bw,
                  const float* __restrict__ bias, const float* __restrict__ Res,
                  float* __restrict__ Cout, int M, int N, int Kd)
{
    __shared__ __align__(16) float As[2][BK][BM+4];
    __shared__ __align__(16) float Bs[2][BK][BN];

    int tM = blockIdx.y * BM;
    int tN = blockIdx.x * BN;
    int tid = threadIdx.x;

    int arow[2], akq[2];
    const float* aptr[2];
    int bkr[2], bnq[2];
    const float* bptr[2];
#pragma unroll
    for (int l = 0; l < 2; l++) {
        int idx = tid + 256*l;
        arow[l] = idx >> 2; akq[l] = idx & 3;
        aptr[l] = A + (size_t)(tM + arow[l])*Kd + akq[l]*4;
        bkr[l] = idx >> 5; bnq[l] = idx & 31;
        bptr[l] = Bw + (size_t)bkr[l]*N + tN + bnq[l]*4;
    }

#pragma unroll
    for (int l = 0; l < 2; l++) {
        float4 v = *(const float4*)(aptr[l]);
        As[0][akq[l]*4+0][arow[l]] = v.x; As[0][akq[l]*4+1][arow[l]] = v.y;
        As[0][akq[l]*4+2][arow[l]] = v.z; As[0][akq[l]*4+3][arow[l]] = v.w;
        *(float4*)&Bs[0][bkr[l]][bnq[l]*4] = *(const float4*)(bptr[l]);
    }
    __syncthreads();

    int tx = tid & 15, ty = tid >> 4;
    float acc[8][8];
#pragma unroll
    for (int i = 0; i < 8; i++)
#pragma unroll
        for (int j = 0; j < 8; j++) acc[i][j] = 0.f;

    int nIter = Kd / BK;
    int cur = 0;
    for (int it = 0; it < nIter; it++) {
        float4 av[2], bv[2];
        bool hasNext = (it + 1 < nIter);
        if (hasNext) {
            size_t koff = (size_t)(it + 1) * BK;
#pragma unroll
            for (int l = 0; l < 2; l++) {
                av[l] = *(const float4*)(aptr[l] + koff);
                bv[l] = *(const float4*)(bptr[l] + koff * N);
            }
        }
        const float* asb = &As[cur][0][0];
        const float* bsb = &Bs[cur][0][0];
#pragma unroll
        for (int k = 0; k < BK; k++) {
            float a[8], b[8];
            *(float4*)&a[0] = *(const float4*)(asb + k*(BM+4) + ty*8);
            *(float4*)&a[4] = *(const float4*)(asb + k*(BM+4) + ty*8 + 4);
            *(float4*)&b[0] = *(const float4*)(bsb + k*BN + tx*8);
            *(float4*)&b[4] = *(const float4*)(bsb + k*BN + tx*8 + 4);
#pragma unroll
            for (int i = 0; i < 8; i++)
#pragma unroll
                for (int j = 0; j < 8; j++) acc[i][j] += a[i]*b[j];
        }
        if (hasNext) {
            int nxt = cur ^ 1;
#pragma unroll
            for (int l = 0; l < 2; l++) {
                As[nxt][akq[l]*4+0][arow[l]] = av[l].x;
                As[nxt][akq[l]*4+1][arow[l]] = av[l].y;
                As[nxt][akq[l]*4+2][arow[l]] = av[l].z;
                As[nxt][akq[l]*4+3][arow[l]] = av[l].w;
                *(float4*)&Bs[nxt][bkr[l]][bnq[l]*4] = bv[l];
            }
            __syncthreads();
            cur = nxt;
        }
    }

    float4 bv0 = *(const float4*)(bias + tN + tx*8);
    float4 bv1 = *(const float4*)(bias + tN + tx*8 + 4);
#pragma unroll
    for (int i = 0; i < 8; i++) {
        int rloc = tM + ty*8 + i;
        float o[8];
        o[0]=acc[i][0]+bv0.x; o[1]=acc[i][1]+bv0.y; o[2]=acc[i][2]+bv0.z; o[3]=acc[i][3]+bv0.w;
        o[4]=acc[i][4]+bv1.x; o[5]=acc[i][5]+bv1.y; o[6]=acc[i][6]+bv1.z; o[7]=acc[i][7]+bv1.w;
        size_t coff = (size_t)rloc*N + tN + tx*8;
        if (MODE == 1) {
            const float* rr = Res + coff;
#pragma unroll
            for (int j = 0; j < 8; j++) o[j] += rr[j];
        }
        *(float4*)(Cout + coff)     = make_float4(o[0],o[1],o[2],o[3]);
        *(float4*)(Cout + coff + 4) = make_float4(o[4],o[5],o[6],o[7]);
    }
}

// ---------------- TF32 tensor-core grouped GEMM (MoE only, post-router) ----------
// mma.sync.aligned.m16n8k8.row.col.f32.tf32.tf32.f32
// MODE 2: hid[p0+r] = relu(gather(A, perm)@W1[e] + b1[e])
// MODE 3: ye[perm[p0+r]] = wts * (hid[p0+r]@W2[e] + b2[e])
#define TBM 128
#define TBN 128
#define TBK 16
#define ASTR 20    // A smem row stride (uint32): banks (20r+k)%32 conflict-free
#define BSTR 136   // B smem k stride  (uint32): banks (8k+c)%32  conflict-free

__device__ __forceinline__ uint32_t f2tf(float f) {
    uint32_t r; asm("cvt.rna.tf32.f32 %0, %1;" : "=r"(r) : "f"(f)); return r;
}

#define MMA_TF32(D, A4, B0, B1) \
    asm volatile("mma.sync.aligned.m16n8k8.row.col.f32.tf32.tf32.f32 " \
        "{%0,%1,%2,%3}, {%4,%5,%6,%7}, {%8,%9}, {%0,%1,%2,%3};" \
        : "+f"((D)[0]), "+f"((D)[1]), "+f"((D)[2]), "+f"((D)[3]) \
        : "r"((A4)[0]), "r"((A4)[1]), "r"((A4)[2]), "r"((A4)[3]), \
          "r"(B0), "r"(B1))

template<int MODE>
__global__ __launch_bounds__(256, 2)
void tgemm_kernel(const float* __restrict__ A, const float* __restrict__ Bw,
                  const float* __restrict__ bias, float* __restrict__ Cout,
                  int N, int Kd,
                  const int* __restrict__ perm, const int* __restrict__ eoff,
                  const float* __restrict__ wts)
{
    __shared__ __align__(16) uint32_t Asu[2][TBM*ASTR];   // 20.5 KB
    __shared__ __align__(16) uint32_t Bsu[2][TBK*BSTR];   // 17.4 KB
    __shared__ int rowIdx[TBM];

    int e = blockIdx.z;
    int p0 = eoff[e];
    int Mloc = eoff[e+1] - p0;
    int tM = blockIdx.y * TBM;
    if (tM >= Mloc) return;
    const float* Bp = Bw + (size_t)e * Kd * N;
    const float* biasp = bias + (size_t)e * N;
    int tN = blockIdx.x * TBN;
    int tid = threadIdx.x;

    if (tid < TBM) {
        int r = tM + tid;
        int src = -1;
        if (r < Mloc) src = (MODE == 2) ? (perm[p0 + r] >> 1) : (p0 + r);
        rowIdx[tid] = src;
    }
    __syncthreads();

    const float* aptr[2]; int arow[2], akq[2];
    const float* bptr[2]; int bkr[2], bnq[2];
#pragma unroll
    for (int l = 0; l < 2; l++) {
        int idx = tid + 256*l;
        arow[l] = idx >> 2; akq[l] = idx & 3;
        int src = rowIdx[arow[l]];
        aptr[l] = (src >= 0) ? (A + (size_t)src*Kd + akq[l]*4) : nullptr;
        bkr[l] = idx >> 5; bnq[l] = idx & 31;
        bptr[l] = Bp + (size_t)bkr[l]*N + tN + bnq[l]*4;
    }

    // prologue: tile 0 -> buffer 0 (convert to tf32 with RNA rounding)
#pragma unroll
    for (int l = 0; l < 2; l++) {
        float4 v = make_float4(0.f,0.f,0.f,0.f);
        if (aptr[l]) v = *(const float4*)(aptr[l]);
        *(uint4*)&Asu[0][arow[l]*ASTR + akq[l]*4] =
            make_uint4(f2tf(v.x), f2tf(v.y), f2tf(v.z), f2tf(v.w));
        float4 w = *(const float4*)(bptr[l]);
        *(uint4*)&Bsu[0][bkr[l]*BSTR + bnq[l]*4] =
            make_uint4(f2tf(w.x), f2tf(w.y), f2tf(w.z), f2tf(w.w));
    }
    __syncthreads();

    int lane = tid & 31, warp = tid >> 5;
    int wm = warp & 3, wn = warp >> 2;     // 4x2 warp grid, warp tile 32x64
    int lg = lane >> 2, lk = lane & 3;

    float acc[2][8][4];
#pragma unroll
    for (int a = 0; a < 2; a++)
#pragma unroll
        for (int b = 0; b < 8; b++)
#pragma unroll
            for (int c = 0; c < 4; c++) acc[a][b][c] = 0.f;

    int nIter = Kd / TBK;
    int cur = 0;
    for (int it = 0; it < nIter; it++) {
        float4 av[2], bv[2];
        bool hasNext = (it + 1 < nIter);
        if (hasNext) {
            size_t koff = (size_t)(it + 1) * TBK;
#pragma unroll
            for (int l = 0; l < 2; l++) {
                av[l] = make_float4(0.f,0.f,0.f,0.f);
                if (aptr[l]) av[l] = *(const float4*)(aptr[l] + koff);
                bv[l] = *(const float4*)(bptr[l] + koff * N);
            }
        }
        const uint32_t* As = Asu[cur];
        const uint32_t* Bs = Bsu[cur];
#pragma unroll
        for (int k8 = 0; k8 < TBK; k8 += 8) {
            int kk = k8 + lk;
            uint32_t af[2][4];
#pragma unroll
            for (int mt = 0; mt < 2; mt++) {
                int rr = wm*32 + mt*16 + lg;
                af[mt][0] = As[rr*ASTR + kk];
                af[mt][1] = As[(rr+8)*ASTR + kk];
                af[mt][2] = As[rr*ASTR + kk + 4];
                af[mt][3] = As[(rr+8)*ASTR + kk + 4];
            }
#pragma unroll
            for (int nt = 0; nt < 8; nt++) {
                int cc = wn*64 + nt*8 + lg;
                uint32_t b0 = Bs[kk*BSTR + cc];
                uint32_t b1 = Bs[(kk+4)*BSTR + cc];
                MMA_TF32(acc[0][nt], af[0], b0, b1);
                MMA_TF32(acc[1][nt], af[1], b0, b1);
            }
        }
        if (hasNext) {
            int nxt = cur ^ 1;
#pragma unroll
            for (int l = 0; l < 2; l++) {
                *(uint4*)&Asu[nxt][arow[l]*ASTR + akq[l]*4] =
                    make_uint4(f2tf(av[l].x), f2tf(av[l].y), f2tf(av[l].z), f2tf(av[l].w));
                *(uint4*)&Bsu[nxt][bkr[l]*BSTR + bnq[l]*4] =
                    make_uint4(f2tf(bv[l].x), f2tf(bv[l].y), f2tf(bv[l].z), f2tf(bv[l].w));
            }
            __syncthreads();
            cur = nxt;
        }
    }

    // epilogue: c0,c1 -> row lg ; c2,c3 -> row lg+8 ; cols 2*lk, 2*lk+1
#pragma unroll
    for (int mt = 0; mt < 2; mt++) {
#pragma unroll
        for (int half = 0; half < 2; half++) {
            int rloc = wm*32 + mt*16 + half*8 + lg;
            if (tM + rloc >= Mloc) continue;
            int orow; float scale = 1.f;
            if (MODE == 2) {
                orow = p0 + tM + rloc;
            } else {
                int a = perm[p0 + tM + rloc];
                orow = a;
                scale = wts[a];
            }
            float* crow = Cout + (size_t)orow*N;
#pragma unroll
            for (int nt = 0; nt < 8; nt++) {
                int col = tN + wn*64 + nt*8 + lk*2;
                float v0 = acc[mt][nt][half*2+0] + biasp[col];
                float v1 = acc[mt][nt][half*2+1] + biasp[col+1];
                if (MODE == 2) { v0 = fmaxf(v0, 0.f); v1 = fmaxf(v1, 0.f); }
                else           { v0 *= scale; v1 *= scale; }
                *(float2*)(crow + col) = make_float2(v0, v1);
            }
        }
    }
}

// ---------------- flash attention (fp32, causal), 64x64 tiles, D=64 ----------------
#define ATTN_SMEM ((64*65*2 + 64*64)*4)

__global__ __launch_bounds__(256)
void attn_kernel(const float* __restrict__ qkv, float* __restrict__ y)
{
    extern __shared__ float sm[];
    float* Qs  = sm;
    float* KPs = sm + 64*65;
    float* Vs  = sm + 2*64*65;

    int tid = threadIdx.x;
    int tx = tid & 15, ty = tid >> 4;
    int bh = blockIdx.y;
    int b = bh / HNUM, h = bh % HNUM;
    int qt = blockIdx.x;
    const float* qb = qkv + (size_t)b*TSEQ*QKVDIM + h*DHEAD;
    const float* kb = qb + CDIM;
    const float* vb = qb + 2*CDIM;

#pragma unroll
    for (int p = 0; p < 4; p++) {
        int r = p*16 + ty;
        float4 v = *(const float4*)(qb + (size_t)(qt*64 + r)*QKVDIM + tx*4);
        Qs[(tx*4+0)*65 + r] = v.x; Qs[(tx*4+1)*65 + r] = v.y;
        Qs[(tx*4+2)*65 + r] = v.z; Qs[(tx*4+3)*65 + r] = v.w;
    }

    float o[4][4];
    float mrow[4], lrow[4];
#pragma unroll
    for (int i = 0; i < 4; i++) {
        mrow[i] = -INFINITY; lrow[i] = 0.f;
#pragma unroll
        for (int j = 0; j < 4; j++) o[i][j] = 0.f;
    }

    for (int kt = 0; kt <= qt; kt++) {
        __syncthreads();
#pragma unroll
        for (int p = 0; p < 4; p++) {
            int r = p*16 + ty;
            float4 kv = *(const float4*)(kb + (size_t)(kt*64 + r)*QKVDIM + tx*4);
            KPs[(tx*4+0)*65 + r] = kv.x; KPs[(tx*4+1)*65 + r] = kv.y;
            KPs[(tx*4+2)*65 + r] = kv.z; KPs[(tx*4+3)*65 + r] = kv.w;
            float4 vv = *(const float4*)(vb + (size_t)(kt*64 + r)*QKVDIM + tx*4);
            *(float4*)&Vs[r*64 + tx*4] = vv;
        }
        __syncthreads();

        float s[4][4];
#pragma unroll
        for (int i = 0; i < 4; i++)
#pragma unroll
            for (int j = 0; j < 4; j++) s[i][j] = 0.f;
#pragma unroll
        for (int d = 0; d < 64; d++) {
            float a[4], bq[4];
#pragma unroll
            for (int i = 0; i < 4; i++) a[i]  = Qs [d*65 + ty*4 + i];
#pragma unroll
            for (int j = 0; j < 4; j++) bq[j] = KPs[d*65 + tx*4 + j];
#pragma unroll
            for (int i = 0; i < 4; i++)
#pragma unroll
                for (int j = 0; j < 4; j++) s[i][j] += a[i]*bq[j];
        }
#pragma unroll
        for (int i = 0; i < 4; i++)
#pragma unroll
            for (int j = 0; j < 4; j++) s[i][j] *= 0.125f;
        if (kt == qt) {
#pragma unroll
            for (int i = 0; i < 4; i++)
#pragma unroll
                for (int j = 0; j < 4; j++)
                    if (tx*4 + j > ty*4 + i) s[i][j] = -INFINITY;
        }
        __syncthreads();

#pragma unroll
        for (int i = 0; i < 4; i++) {
            float mx = fmaxf(fmaxf(s[i][0], s[i][1]), fmaxf(s[i][2], s[i][3]));
#pragma unroll
            for (int off = 1; off < 16; off <<= 1)
                mx = fmaxf(mx, __shfl_xor_sync(0xffffffffu, mx, off));
            float mnew = fmaxf(mrow[i], mx);
            float corr = __expf(mrow[i] - mnew);
            float rs = 0.f;
#pragma unroll
            for (int j = 0; j < 4; j++) { s[i][j] = __expf(s[i][j] - mnew); rs += s[i][j]; }
#pragma unroll
            for (int off = 1; off < 16; off <<= 1)
                rs += __shfl_xor_sync(0xffffffffu, rs, off);
            lrow[i] = lrow[i]*corr + rs;
            mrow[i] = mnew;
#pragma unroll
            for (int j = 0; j < 4; j++) o[i][j] *= corr;
#pragma unroll
            for (int j = 0; j < 4; j++)
                KPs[(tx*4+j)*65 + (ty*4+i)] = s[i][j];
        }
        __syncthreads();

#pragma unroll
        for (int ss = 0; ss < 64; ss++) {
            float a[4], bv[4];
#pragma unroll
            for (int i = 0; i < 4; i++) a[i] = KPs[ss*65 + ty*4 + i];
            *(float4*)bv = *(const float4*)&Vs[ss*64 + tx*4];
#pragma unroll
            for (int i = 0; i < 4; i++)
#pragma unroll
                for (int j = 0; j < 4; j++) o[i][j] += a[i]*bv[j];
        }
    }

#pragma unroll
    for (int i = 0; i < 4; i++) {
        float inv = 1.0f / lrow[i];
        int row = qt*64 + ty*4 + i;
        float4 ov = make_float4(o[i][0]*inv, o[i][1]*inv, o[i][2]*inv, o[i][3]*inv);
        *(float4*)(y + ((size_t)b*TSEQ + row)*CDIM + h*DHEAD + tx*4) = ov;
    }
}

// ---------------- router: one block per token, top-2 + softmax ----------------
__global__ void router_kernel(const float* __restrict__ z, const float* __restrict__ Wr,
                              const float* __restrict__ br, int* __restrict__ eidx,
                              float* __restrict__ wts, int* __restrict__ cnt)
{
    int n = blockIdx.x, tid = threadIdx.x;
    float acc[EXP];
#pragma unroll
    for (int e = 0; e < EXP; e++) acc[e] = 0.f;
    const float* zr = z + (size_t)n*CDIM;
    for (int c = tid; c < CDIM; c += 256) {
        float zv = zr[c];
        const float* wr = Wr + c*EXP;
#pragma unroll
        for (int e = 0; e < EXP; e++) acc[e] += zv * wr[e];
    }
#pragma unroll
    for (int e = 0; e < EXP; e++)
#pragma unroll
        for (int off = 16; off; off >>= 1)
            acc[e] += __shfl_xor_sync(0xffffffffu, acc[e], off);
    __shared__ float red[8][EXP];
    int warp = tid >> 5, lane = tid & 31;
    if (lane == 0)
#pragma unroll
        for (int e = 0; e < EXP; e++) red[warp][e] = acc[e];
    __syncthreads();
    if (tid == 0) {
        float l[EXP];
#pragma unroll
        for (int e = 0; e < EXP; e++) {
            float sv = br[e];
#pragma unroll
            for (int w = 0; w < 8; w++) sv += red[w][e];
            l[e] = sv;
        }
        int i1 = 0;
#pragma unroll
        for (int e = 1; e < EXP; e++) if (l[e] > l[i1]) i1 = e;
        int i2 = -1;
#pragma unroll
        for (int e = 0; e < EXP; e++) {
            if (e == i1) continue;
            if (i2 < 0 || l[e] > l[i2]) i2 = e;
        }
        float e2 = __expf(l[i2] - l[i1]);
        float inv = 1.0f / (1.0f + e2);
        eidx[n*2]   = i1;  eidx[n*2+1] = i2;
        wts [n*2]   = inv; wts [n*2+1] = e2*inv;
        atomicAdd(&cnt[i1], 1);
        atomicAdd(&cnt[i2], 1);
    }
}

__global__ void zero_kernel(int* cnt) { if (threadIdx.x < EXP) cnt[threadIdx.x] = 0; }

__global__ void scan_kernel(const int* __restrict__ cnt, int* __restrict__ eoff,
                            int* __restrict__ fill)
{
    if (threadIdx.x == 0) {
        int s = 0;
        for (int e = 0; e < EXP; e++) { eoff[e] = s; fill[e] = s; s += cnt[e]; }
        eoff[EXP] = s;
    }
}

__global__ void scatter_kernel(const int* __restrict__ eidx, int* __restrict__ fill,
                               int* __restrict__ perm)
{
    int a = blockIdx.x*256 + threadIdx.x;
    if (a >= NSLOT) return;
    int e = eidx[a];
    int pos = atomicAdd(&fill[e], 1);
    perm[pos] = a;
}

// ---------------- final combine: out = x1 + ye[tok,0] + ye[tok,1] ----------------
__global__ void combine_kernel(const float* __restrict__ x1, const float* __restrict__ ye,
                               float* __restrict__ out)
{
    int i = blockIdx.x*256 + threadIdx.x;
    if (i >= NTOK*(CDIM/4)) return;
    int n = i / (CDIM/4), c4 = i % (CDIM/4);
    size_t co = (size_t)c4*4;
    float4 a  = *(const float4*)(x1 + (size_t)n*CDIM + co);
    float4 y0 = *(const float4*)(ye + (size_t)(n*2)  *CDIM + co);
    float4 y1 = *(const float4*)(ye + (size_t)(n*2+1)*CDIM + co);
    a.x += y0.x + y1.x; a.y += y0.y + y1.y;
    a.z += y0.z + y1.z; a.w += y0.w + y1.w;
    *(float4*)(out + (size_t)n*CDIM + co) = a;
}

// ---------------- launch ----------------
extern "C" void kernel_launch(void* const* d_in, const int* in_sizes, int n_in,
                              void* d_out, int out_size)
{
    (void)in_sizes; (void)n_in; (void)out_size;
    const float* x      = (const float*)d_in[0];
    const float* ln1_g  = (const float*)d_in[1];
    const float* ln1_b  = (const float*)d_in[2];
    const float* Wqkv   = (const float*)d_in[3];
    const float* bqkv   = (const float*)d_in[4];
    const float* Wproj  = (const float*)d_in[5];
    const float* bproj  = (const float*)d_in[6];
    const float* ln2_g  = (const float*)d_in[7];
    const float* ln2_b  = (const float*)d_in[8];
    const float* Wr     = (const float*)d_in[9];
    const float* br     = (const float*)d_in[10];
    const float* W1     = (const float*)d_in[11];
    const float* b1     = (const float*)d_in[12];
    const float* W2     = (const float*)d_in[13];
    const float* b2     = (const float*)d_in[14];
    float* out = (float*)d_out;

    float *h,*qkv,*y,*x1,*z,*hid,*ye,*wts;
    int *eidx,*cnt,*eoff,*fill,*perm;
    cudaGetSymbolAddress((void**)&h,   g_h);
    cudaGetSymbolAddress((void**)&qkv, g_qkv);
    cudaGetSymbolAddress((void**)&y,   g_y);
    cudaGetSymbolAddress((void**)&x1,  g_x1);
    cudaGetSymbolAddress((void**)&z,   g_z);
    cudaGetSymbolAddress((void**)&hid, g_hid);
    cudaGetSymbolAddress((void**)&ye,  g_ye);
    cudaGetSymbolAddress((void**)&wts, g_wts);
    cudaGetSymbolAddress((void**)&eidx,g_eidx);
    cudaGetSymbolAddress((void**)&cnt, g_cnt);
    cudaGetSymbolAddress((void**)&eoff,g_eoff);
    cudaGetSymbolAddress((void**)&fill,g_fill);
    cudaGetSymbolAddress((void**)&perm,g_perm);

    cudaFuncSetAttribute(attn_kernel, cudaFuncAttributeMaxDynamicSharedMemorySize, ATTN_SMEM);

    // 1. LN1
    ln_kernel<<<NTOK, 256>>>(x, ln1_g, ln1_b, h);
    // 2. QKV projection (fp32: feeds router-critical path)
    sgemm_kernel<0><<<dim3(QKVDIM/BN, NTOK/BM), 256>>>(h, Wqkv, bqkv, nullptr, qkv,
                                                       NTOK, QKVDIM, CDIM);
    // 3. causal flash attention (fp32)
    attn_kernel<<<dim3(TSEQ/64, BATCH*HNUM), 256, ATTN_SMEM>>>(qkv, y);
    // 4. output projection + residual (fp32: feeds router-critical path)
    sgemm_kernel<1><<<dim3(CDIM/BN, NTOK/BM), 256>>>(y, Wproj, bproj, x, x1,
                                                     NTOK, CDIM, CDIM);
    // 5. LN2
    ln_kernel<<<NTOK, 256>>>(x1, ln2_g, ln2_b, z);
    // 6. router top-2 (exact fp32 z -> deterministic expert choice)
    zero_kernel<<<1, 32>>>(cnt);
    router_kernel<<<NTOK, 256>>>(z, Wr, br, eidx, wts, cnt);
    scan_kernel<<<1, 32>>>(cnt, eoff, fill);
    scatter_kernel<<<(NSLOT+255)/256, 256>>>(eidx, fill, perm);
    // 7. grouped expert GEMM1: TF32 tensor cores (gather + relu)
    tgemm_kernel<2><<<dim3(DFF/TBN, NSLOT/TBM, EXP), 256>>>(z, W1, b1, hid,
                                                            DFF, CDIM, perm, eoff, nullptr);
    // 8. grouped expert GEMM2: TF32 tensor cores (scatter with gate weight)
    tgemm_kernel<3><<<dim3(CDIM/TBN, NSLOT/TBM, EXP), 256>>>(hid, W2, b2, ye,
                                                             CDIM, DFF, perm, eoff, wts);
    // 9. combine
    combine_kernel<<<(NTOK*(CDIM/4)+255)/256, 256>>>(x1, ye, out);
}